// round 1
// baseline (speedup 1.0000x reference)
#include <cuda_runtime.h>
#include <cuda_bf16.h>

#define H      1024
#define NJ     8          // H / (32 lanes * 4 floats)
#define TPB    256
#define WPB    (TPB / 32)
#define NBLK   296        // 2 CTAs per SM * 148 SMs

// Scratch: per-block partial context sums (allocation-free __device__ global).
__device__ float4 g_partial[NBLK * (H / 4)];

__global__ __launch_bounds__(TPB, 2)
void cos_attn_main(const float* __restrict__ q,
                   const float* __restrict__ keys,
                   int S)
{
    const int lane = threadIdx.x & 31;
    const int warp = threadIdx.x >> 5;
    const int gw   = blockIdx.x * WPB + warp;
    const int nw   = gridDim.x * WPB;

    // ---- load q into registers (all warps hit L1/L2 after first) ----
    const float4* q4 = reinterpret_cast<const float4*>(q);
    float4 qv[NJ];
#pragma unroll
    for (int j = 0; j < NJ; j++)
        qv[j] = q4[j * 32 + lane];

    float qs = 0.f;
#pragma unroll
    for (int j = 0; j < NJ; j++)
        qs += qv[j].x*qv[j].x + qv[j].y*qv[j].y + qv[j].z*qv[j].z + qv[j].w*qv[j].w;
#pragma unroll
    for (int o = 16; o > 0; o >>= 1)
        qs += __shfl_xor_sync(0xffffffffu, qs, o);
    const float inv_qn = rsqrtf(qs);

    // ---- accumulator: 32 floats per lane = full 1024-wide context slice ----
    float4 acc[NJ];
#pragma unroll
    for (int j = 0; j < NJ; j++) acc[j] = make_float4(0.f, 0.f, 0.f, 0.f);

    // ---- one warp per key row, grid-stride; single HBM pass over keys ----
    for (int r = gw; r < S; r += nw) {
        const float4* krow = reinterpret_cast<const float4*>(keys) + (size_t)r * (H / 4);
        float4 kv[NJ];
#pragma unroll
        for (int j = 0; j < NJ; j++)            // 8 independent LDG.128 (MLP)
            kv[j] = krow[j * 32 + lane];

        float dot = 0.f, ks = 0.f;
#pragma unroll
        for (int j = 0; j < NJ; j++) {
            dot += kv[j].x*qv[j].x + kv[j].y*qv[j].y + kv[j].z*qv[j].z + kv[j].w*qv[j].w;
            ks  += kv[j].x*kv[j].x + kv[j].y*kv[j].y + kv[j].z*kv[j].z + kv[j].w*kv[j].w;
        }
#pragma unroll
        for (int o = 16; o > 0; o >>= 1) {
            dot += __shfl_xor_sync(0xffffffffu, dot, o);
            ks  += __shfl_xor_sync(0xffffffffu, ks,  o);
        }

        const float w = dot * inv_qn * rsqrtf(ks);
#pragma unroll
        for (int j = 0; j < NJ; j++) {
            acc[j].x += w * kv[j].x;
            acc[j].y += w * kv[j].y;
            acc[j].z += w * kv[j].z;
            acc[j].w += w * kv[j].w;
        }
    }

    // ---- block reduction: stage per-warp slices in smem, tree-free sum ----
    __shared__ float4 s_red[WPB][H / 4];        // 8 * 256 * 16B = 32 KB
#pragma unroll
    for (int j = 0; j < NJ; j++)
        s_red[warp][j * 32 + lane] = acc[j];
    __syncthreads();

    // thread t sums the 8 warp copies of float4-column t
    {
        const int t = threadIdx.x;              // 0..255, covers H/4 columns
        float4 s = s_red[0][t];
#pragma unroll
        for (int w2 = 1; w2 < WPB; w2++) {
            float4 v = s_red[w2][t];
            s.x += v.x; s.y += v.y; s.z += v.z; s.w += v.w;
        }
        g_partial[blockIdx.x * (H / 4) + t] = s;
    }
}

// Deterministic final reduction: sum NBLK partials per column.
__global__ void cos_attn_reduce(float* __restrict__ out)
{
    const int c = blockIdx.x * 32 + threadIdx.x;   // 0..1023 scalar column
    const float* p = reinterpret_cast<const float*>(g_partial);
    float s = 0.f;
#pragma unroll 8
    for (int b = 0; b < NBLK; b++)
        s += p[(size_t)b * H + c];
    out[c] = s;
}

extern "C" void kernel_launch(void* const* d_in, const int* in_sizes, int n_in,
                              void* d_out, int out_size)
{
    const float* query = (const float*)d_in[0];   // [1, 1024]
    const float* keys  = (const float*)d_in[1];   // [S, 1024]
    float* out = (float*)d_out;                   // [1, 1024]

    const int S = in_sizes[1] / H;

    cos_attn_main<<<NBLK, TPB>>>(query, keys, S);
    cos_attn_reduce<<<32, 32>>>(out);
}

// round 5
// speedup vs baseline: 1.1187x; 1.1187x over previous
#include <cuda_runtime.h>
#include <cuda_bf16.h>

#define H      1024
#define NJ     8          // H / (32 lanes * 4 floats)
#define TPB    256
#define WPB    (TPB / 32)
#define NBLK   296        // 2 CTAs per SM * 148 SMs
#define BPAD   304        // NBLK padded (column stride, avoids set aliasing)

// Transposed partials: column c occupies BPAD consecutive floats.
// g_partialT[c * BPAD + b] = block b's partial sum for output column c.
__device__ float g_partialT[H * BPAD];

__global__ __launch_bounds__(TPB, 2)
void cos_attn_main(const float* __restrict__ q,
                   const float* __restrict__ keys,
                   int S)
{
    const int lane = threadIdx.x & 31;
    const int warp = threadIdx.x >> 5;
    const int gw   = blockIdx.x * WPB + warp;
    const int nw   = gridDim.x * WPB;

    // ---- q into registers (L1/L2 hit after first warp) ----
    const float4* q4 = reinterpret_cast<const float4*>(q);
    float4 qv[NJ];
#pragma unroll
    for (int j = 0; j < NJ; j++)
        qv[j] = q4[j * 32 + lane];

    float qs = 0.f;
#pragma unroll
    for (int j = 0; j < NJ; j++)
        qs += qv[j].x*qv[j].x + qv[j].y*qv[j].y + qv[j].z*qv[j].z + qv[j].w*qv[j].w;
#pragma unroll
    for (int o = 16; o > 0; o >>= 1)
        qs += __shfl_xor_sync(0xffffffffu, qs, o);
    const float inv_qn = rsqrtf(qs);

    // ---- accumulator: full 1024-wide context slice per warp ----
    float4 acc[NJ];
#pragma unroll
    for (int j = 0; j < NJ; j++) acc[j] = make_float4(0.f, 0.f, 0.f, 0.f);

    // ---- one warp per key row, grid-stride; single pass over keys ----
    for (int r = gw; r < S; r += nw) {
        const float4* krow = reinterpret_cast<const float4*>(keys) + (size_t)r * (H / 4);
        float4 kv[NJ];
#pragma unroll
        for (int j = 0; j < NJ; j++)            // 8 independent LDG.128
            kv[j] = krow[j * 32 + lane];

        float dot = 0.f, ks = 0.f;
#pragma unroll
        for (int j = 0; j < NJ; j++) {
            dot += kv[j].x*qv[j].x + kv[j].y*qv[j].y + kv[j].z*qv[j].z + kv[j].w*qv[j].w;
            ks  += kv[j].x*kv[j].x + kv[j].y*kv[j].y + kv[j].z*kv[j].z + kv[j].w*kv[j].w;
        }
#pragma unroll
        for (int o = 16; o > 0; o >>= 1) {
            dot += __shfl_xor_sync(0xffffffffu, dot, o);
            ks  += __shfl_xor_sync(0xffffffffu, ks,  o);
        }

        const float w = dot * inv_qn * rsqrtf(ks);
#pragma unroll
        for (int j = 0; j < NJ; j++) {
            acc[j].x += w * kv[j].x;
            acc[j].y += w * kv[j].y;
            acc[j].z += w * kv[j].z;
            acc[j].w += w * kv[j].w;
        }
    }

    // ---- block reduction: stage per-warp slices in smem ----
    __shared__ float4 s_red[WPB][H / 4];        // 32 KB
#pragma unroll
    for (int j = 0; j < NJ; j++)
        s_red[warp][j * 32 + lane] = acc[j];
    __syncthreads();

    // thread t sums the 8 warp copies of float4-column t, then writes
    // TRANSPOSED partials (4 scalar STGs, stride BPAD floats).
    {
        const int t = threadIdx.x;              // 0..255 -> scalar cols 4t..4t+3
        float4 s = s_red[0][t];
#pragma unroll
        for (int w2 = 1; w2 < WPB; w2++) {
            float4 v = s_red[w2][t];
            s.x += v.x; s.y += v.y; s.z += v.z; s.w += v.w;
        }
        const int b = blockIdx.x;
        g_partialT[(4*t + 0) * BPAD + b] = s.x;
        g_partialT[(4*t + 1) * BPAD + b] = s.y;
        g_partialT[(4*t + 2) * BPAD + b] = s.z;
        g_partialT[(4*t + 3) * BPAD + b] = s.w;
    }
}

// Warp-per-column reduce: 1024 warps, coalesced consecutive reads, fixed
// deterministic summation order.
__global__ __launch_bounds__(256)
void cos_attn_reduce(float* __restrict__ out)
{
    const int gwarp = (blockIdx.x * blockDim.x + threadIdx.x) >> 5; // 0..1023
    const int lane  = threadIdx.x & 31;

    const float* col = g_partialT + (size_t)gwarp * BPAD;
    float s = 0.f;
#pragma unroll
    for (int i = 0; i < (NBLK + 31) / 32; i++) {    // 10 independent loads
        int b = lane + i * 32;
        if (b < NBLK) s += col[b];
    }
#pragma unroll
    for (int o = 16; o > 0; o >>= 1)
        s += __shfl_xor_sync(0xffffffffu, s, o);

    if (lane == 0) out[gwarp] = s;
}

extern "C" void kernel_launch(void* const* d_in, const int* in_sizes, int n_in,
                              void* d_out, int out_size)
{
    const float* query = (const float*)d_in[0];   // [1, 1024]
    const float* keys  = (const float*)d_in[1];   // [S, 1024]
    float* out = (float*)d_out;                   // [1, 1024]

    const int S = in_sizes[1] / H;

    cos_attn_main<<<NBLK, TPB>>>(query, keys, S);
    cos_attn_reduce<<<(H * 32) / 256, 256>>>(out);  // 32 blocks x 8 warps
}

// round 6
// speedup vs baseline: 1.2667x; 1.1323x over previous
#include <cuda_runtime.h>
#include <cuda_bf16.h>

#define H      1024
#define H4     (H / 4)
#define NJ     8              // H / (32 lanes * 4 floats)
#define TPB    384
#define WPB    (TPB / 32)     // 12 warps
#define NBLK   148            // 1 CTA per SM -> guaranteed single resident wave
#define NW     (NBLK * WPB)   // 1776 warps

// Per-block partial context sums + monotonic barrier counter (never reset:
// epoch = ticket / NBLK keeps replays deterministic without a reset race).
__device__ float4 g_partial[NBLK][H4];
__device__ int    g_count;    // zero-initialized at module load

__device__ __forceinline__ int atom_add_release(int* p, int v) {
    int o;
    asm volatile("atom.add.release.gpu.s32 %0, [%1], %2;"
                 : "=r"(o) : "l"(p), "r"(v) : "memory");
    return o;
}
__device__ __forceinline__ int ld_acquire(int* p) {
    int v;
    asm volatile("ld.acquire.gpu.b32 %0, [%1];" : "=r"(v) : "l"(p) : "memory");
    return v;
}

__global__ __launch_bounds__(TPB, 1)
void cos_attn_fused(const float* __restrict__ q,
                    const float* __restrict__ keys,
                    float* __restrict__ out, int S)
{
    const int tid  = threadIdx.x;
    const int lane = tid & 31;
    const int warp = tid >> 5;
    const int gw   = blockIdx.x * WPB + warp;

    // ---- q into registers ----
    const float4* q4 = reinterpret_cast<const float4*>(q);
    float4 qv[NJ];
#pragma unroll
    for (int j = 0; j < NJ; j++) qv[j] = q4[j * 32 + lane];

    float qs = 0.f;
#pragma unroll
    for (int j = 0; j < NJ; j++)
        qs += qv[j].x*qv[j].x + qv[j].y*qv[j].y + qv[j].z*qv[j].z + qv[j].w*qv[j].w;
#pragma unroll
    for (int o = 16; o > 0; o >>= 1)
        qs += __shfl_xor_sync(0xffffffffu, qs, o);
    const float inv_qn = rsqrtf(qs);

    float4 acc[NJ];
#pragma unroll
    for (int j = 0; j < NJ; j++) acc[j] = make_float4(0.f, 0.f, 0.f, 0.f);

    // ---- contiguous row chunk per warp, double-buffered prefetch ----
    const int chunk = (S + NW - 1) / NW;
    const int r0    = gw * chunk;
    const int r1    = min(S, r0 + chunk);

    const float4* kbase = reinterpret_cast<const float4*>(keys);

    auto loadrow = [&](float4* dst, int row) {
        const float4* kr = kbase + (size_t)row * H4;
#pragma unroll
        for (int j = 0; j < NJ; j++) dst[j] = kr[j * 32 + lane];
    };
    auto process = [&](const float4* kv) {
        float dot = 0.f, ks = 0.f;
#pragma unroll
        for (int j = 0; j < NJ; j++) {
            dot += kv[j].x*qv[j].x + kv[j].y*qv[j].y + kv[j].z*qv[j].z + kv[j].w*qv[j].w;
            ks  += kv[j].x*kv[j].x + kv[j].y*kv[j].y + kv[j].z*kv[j].z + kv[j].w*kv[j].w;
        }
#pragma unroll
        for (int o = 16; o > 0; o >>= 1) {
            dot += __shfl_xor_sync(0xffffffffu, dot, o);
            ks  += __shfl_xor_sync(0xffffffffu, ks,  o);
        }
        const float w = dot * inv_qn * rsqrtf(ks);
#pragma unroll
        for (int j = 0; j < NJ; j++) {
            acc[j].x += w * kv[j].x;
            acc[j].y += w * kv[j].y;
            acc[j].z += w * kv[j].z;
            acc[j].w += w * kv[j].w;
        }
    };

    float4 A[NJ], B[NJ];
    if (r0 < r1) {
        loadrow(A, r0);
        int r = r0;
        while (true) {
            if (r + 1 < r1) loadrow(B, r + 1);   // prefetch overlaps shfl+acc
            process(A);
            if (++r >= r1) break;
            if (r + 1 < r1) loadrow(A, r + 1);
            process(B);
            if (++r >= r1) break;
        }
    }

    // ---- block reduction over 12 warps, 2 halves of 6 (24 KB smem) ----
    __shared__ float4 s_red[6][H4];
    float4 tot = make_float4(0.f, 0.f, 0.f, 0.f);
#pragma unroll
    for (int half = 0; half < 2; half++) {
        if (warp >= half * 6 && warp < half * 6 + 6) {
#pragma unroll
            for (int j = 0; j < NJ; j++)
                s_red[warp - half * 6][j * 32 + lane] = acc[j];
        }
        __syncthreads();
        if (tid < H4) {
#pragma unroll
            for (int w2 = 0; w2 < 6; w2++) {
                float4 v = s_red[w2][tid];
                tot.x += v.x; tot.y += v.y; tot.z += v.z; tot.w += v.w;
            }
        }
        __syncthreads();
    }
    if (tid < H4)
        g_partial[blockIdx.x][tid] = tot;

    // ---- device-wide barrier: monotonic ticket, release/acquire ----
    __threadfence();
    __syncthreads();
    __shared__ int s_ticket;
    if (tid == 0) s_ticket = atom_add_release(&g_count, 1);
    __syncthreads();
    const int target = (s_ticket / NBLK + 1) * NBLK;

    if (blockIdx.x >= 128) return;   // only 128 blocks do the final reduce

    if (tid == 0) {
        while (ld_acquire(&g_count) < target) __nanosleep(40);
    }
    __syncthreads();
    __threadfence();

    // ---- final reduce: block b sums columns (float4) 2b and 2b+1 ----
    // 128 lanes per column group: lane l reads partial row l (and l+128 if valid),
    // then 4-warp butterfly + smem combine. Fixed order -> deterministic.
    __shared__ float4 s_fin[2][4];
    if (tid < 256) {
        const int grp  = tid >> 7;          // 0 or 1
        const int l    = tid & 127;         // partial-row index
        const int c4   = blockIdx.x * 2 + grp;

        float4 s = g_partial[l][c4];
        if (l < NBLK - 128) {
            float4 v = g_partial[l + 128][c4];
            s.x += v.x; s.y += v.y; s.z += v.z; s.w += v.w;
        }
#pragma unroll
        for (int o = 16; o > 0; o >>= 1) {
            s.x += __shfl_xor_sync(0xffffffffu, s.x, o);
            s.y += __shfl_xor_sync(0xffffffffu, s.y, o);
            s.z += __shfl_xor_sync(0xffffffffu, s.z, o);
            s.w += __shfl_xor_sync(0xffffffffu, s.w, o);
        }
        if (lane == 0) s_fin[grp][(tid >> 5) & 3] = s;
    }
    __syncthreads();
    if (tid < 2) {
        float4 r = s_fin[tid][0];
#pragma unroll
        for (int i = 1; i < 4; i++) {
            float4 v = s_fin[tid][i];
            r.x += v.x; r.y += v.y; r.z += v.z; r.w += v.w;
        }
        reinterpret_cast<float4*>(out)[blockIdx.x * 2 + tid] = r;
    }
}

extern "C" void kernel_launch(void* const* d_in, const int* in_sizes, int n_in,
                              void* d_out, int out_size)
{
    const float* query = (const float*)d_in[0];   // [1, 1024]
    const float* keys  = (const float*)d_in[1];   // [S, 1024]
    float* out = (float*)d_out;                   // [1, 1024]

    const int S = in_sizes[1] / H;

    cos_attn_fused<<<NBLK, TPB>>>(query, keys, out, S);
}

// round 9
// speedup vs baseline: 1.3542x; 1.0691x over previous
#include <cuda_runtime.h>
#include <cuda_bf16.h>

#define H      1024
#define H4     (H / 4)
#define NJ     8              // H / (32 lanes * 4 floats)
#define TPB    256
#define WPB    (TPB / 32)     // 8 warps
#define NBLK   148            // 1 CTA per SM
#define NW     (NBLK * WPB)   // 1184 warps

// Per-block partials + monotonic barrier counter (epoch-based, graph-replay safe).
__device__ float4 g_partial[NBLK][H4];
__device__ int    g_count;

__device__ __forceinline__ int atom_add_release(int* p, int v) {
    int o;
    asm volatile("atom.add.release.gpu.s32 %0, [%1], %2;"
                 : "=r"(o) : "l"(p), "r"(v) : "memory");
    return o;
}
__device__ __forceinline__ int ld_acquire(int* p) {
    int v;
    asm volatile("ld.acquire.gpu.b32 %0, [%1];" : "=r"(v) : "l"(p) : "memory");
    return v;
}

__global__ __launch_bounds__(TPB, 1)
void cos_attn_fused(const float* __restrict__ q,
                    const float* __restrict__ keys,
                    float* __restrict__ out, int S)
{
    const int tid  = threadIdx.x;
    const int lane = tid & 31;
    const int warp = tid >> 5;
    const int gw   = blockIdx.x * WPB + warp;

    // ---- q into registers ----
    const float4* q4 = reinterpret_cast<const float4*>(q);
    float4 qv[NJ];
#pragma unroll
    for (int j = 0; j < NJ; j++) qv[j] = q4[j * 32 + lane];

    float qs = 0.f;
#pragma unroll
    for (int j = 0; j < NJ; j++)
        qs += qv[j].x*qv[j].x + qv[j].y*qv[j].y + qv[j].z*qv[j].z + qv[j].w*qv[j].w;
#pragma unroll
    for (int o = 16; o > 0; o >>= 1)
        qs += __shfl_xor_sync(0xffffffffu, qs, o);
    const float inv_qn = rsqrtf(qs);   // applied once in the epilogue

    float4 acc[NJ];
#pragma unroll
    for (int j = 0; j < NJ; j++) acc[j] = make_float4(0.f, 0.f, 0.f, 0.f);

    // ---- contiguous row chunk per warp ----
    const int chunk = (S + NW - 1) / NW;
    const int r0    = gw * chunk;
    const int r1    = min(S, r0 + chunk);

    const float4* kbase = reinterpret_cast<const float4*>(keys);

    float4 K0[NJ], K1[NJ], K2[NJ], K3[NJ];
#pragma unroll
    for (int j = 0; j < NJ; j++) {
        K0[j] = make_float4(0.f,0.f,0.f,0.f); K1[j] = K0[j];
        K2[j] = K0[j];                        K3[j] = K0[j];
    }

#define LOADROW(BUF, ROW)                                                   \
    do { if ((ROW) < r1) {                                                  \
        const float4* kr_ = kbase + (size_t)(ROW) * H4;                     \
        _Pragma("unroll")                                                   \
        for (int j = 0; j < NJ; j++) BUF[j] = kr_[j * 32 + lane];           \
    } } while (0)

    // Process two rows with interleaved butterflies (4 independent chains).
#define PROC2(BA, BB, RA, RB)                                               \
    do {                                                                    \
        float d0 = 0.f, k0 = 0.f, d1 = 0.f, k1 = 0.f;                       \
        _Pragma("unroll")                                                   \
        for (int j = 0; j < NJ; j++) {                                      \
            d0 += BA[j].x*qv[j].x + BA[j].y*qv[j].y                         \
                + BA[j].z*qv[j].z + BA[j].w*qv[j].w;                        \
            k0 += BA[j].x*BA[j].x + BA[j].y*BA[j].y                         \
                + BA[j].z*BA[j].z + BA[j].w*BA[j].w;                        \
            d1 += BB[j].x*qv[j].x + BB[j].y*qv[j].y                         \
                + BB[j].z*qv[j].z + BB[j].w*qv[j].w;                        \
            k1 += BB[j].x*BB[j].x + BB[j].y*BB[j].y                         \
                + BB[j].z*BB[j].z + BB[j].w*BB[j].w;                        \
        }                                                                   \
        _Pragma("unroll")                                                   \
        for (int o = 16; o > 0; o >>= 1) {                                  \
            d0 += __shfl_xor_sync(0xffffffffu, d0, o);                      \
            k0 += __shfl_xor_sync(0xffffffffu, k0, o);                      \
            d1 += __shfl_xor_sync(0xffffffffu, d1, o);                      \
            k1 += __shfl_xor_sync(0xffffffffu, k1, o);                      \
        }                                                                   \
        const float w0 = ((RA) < r1) ? d0 * rsqrtf(k0) : 0.f;               \
        const float w1 = ((RB) < r1) ? d1 * rsqrtf(k1) : 0.f;               \
        _Pragma("unroll")                                                   \
        for (int j = 0; j < NJ; j++) {                                      \
            acc[j].x += w0 * BA[j].x + w1 * BB[j].x;                        \
            acc[j].y += w0 * BA[j].y + w1 * BB[j].y;                        \
            acc[j].z += w0 * BA[j].z + w1 * BB[j].z;                        \
            acc[j].w += w0 * BA[j].w + w1 * BB[j].w;                        \
        }                                                                   \
    } while (0)

    if (r0 < r1) {
        LOADROW(K0, r0 + 0);
        LOADROW(K1, r0 + 1);
        LOADROW(K2, r0 + 2);
        LOADROW(K3, r0 + 3);
        for (int r = r0; r < r1; r += 4) {
            PROC2(K0, K1, r + 0, r + 1);
            LOADROW(K0, r + 4);
            LOADROW(K1, r + 5);
            if (r + 2 < r1) {
                PROC2(K2, K3, r + 2, r + 3);
                LOADROW(K2, r + 6);
                LOADROW(K3, r + 7);
            }
        }
    }
#undef LOADROW
#undef PROC2

    // ---- block reduction over 8 warps (32 KB smem) ----
    __shared__ float4 s_red[WPB][H4];
#pragma unroll
    for (int j = 0; j < NJ; j++)
        s_red[warp][j * 32 + lane] = acc[j];
    __syncthreads();
    {
        const int t = tid;                    // 0..255 covers H4 columns
        float4 tot = s_red[0][t];
#pragma unroll
        for (int w2 = 1; w2 < WPB; w2++) {
            float4 v = s_red[w2][t];
            tot.x += v.x; tot.y += v.y; tot.z += v.z; tot.w += v.w;
        }
        tot.x *= inv_qn; tot.y *= inv_qn; tot.z *= inv_qn; tot.w *= inv_qn;
        g_partial[blockIdx.x][t] = tot;
    }

    // ---- device-wide barrier: monotonic ticket, release/acquire ----
    __threadfence();
    __syncthreads();
    __shared__ int s_ticket;
    if (tid == 0) s_ticket = atom_add_release(&g_count, 1);
    __syncthreads();
    const int target = (s_ticket / NBLK + 1) * NBLK;

    if (blockIdx.x >= 128) return;            // 128 blocks do the final reduce

    if (tid == 0) {
        while (ld_acquire(&g_count) < target) __nanosleep(40);
    }
    __syncthreads();
    __threadfence();

    // ---- final reduce: block b sums float4 columns 2b, 2b+1 over 148 rows ----
    __shared__ float4 s_fin[2][4];
    {
        const int grp = tid >> 7;             // 0 or 1
        const int l   = tid & 127;            // partial-row index
        const int c4  = blockIdx.x * 2 + grp;

        float4 s = g_partial[l][c4];
        if (l < NBLK - 128) {
            float4 v = g_partial[l + 128][c4];
            s.x += v.x; s.y += v.y; s.z += v.z; s.w += v.w;
        }
#pragma unroll
        for (int o = 16; o > 0; o >>= 1) {
            s.x += __shfl_xor_sync(0xffffffffu, s.x, o);
            s.y += __shfl_xor_sync(0xffffffffu, s.y, o);
            s.z += __shfl_xor_sync(0xffffffffu, s.z, o);
            s.w += __shfl_xor_sync(0xffffffffu, s.w, o);
        }
        if (lane == 0) s_fin[grp][(tid >> 5) & 3] = s;
    }
    __syncthreads();
    if (tid < 2) {
        float4 r = s_fin[tid][0];
#pragma unroll
        for (int i = 1; i < 4; i++) {
            float4 v = s_fin[tid][i];
            r.x += v.x; r.y += v.y; r.z += v.z; r.w += v.w;
        }
        reinterpret_cast<float4*>(out)[blockIdx.x * 2 + tid] = r;
    }
}

extern "C" void kernel_launch(void* const* d_in, const int* in_sizes, int n_in,
                              void* d_out, int out_size)
{
    const float* query = (const float*)d_in[0];   // [1, 1024]
    const float* keys  = (const float*)d_in[1];   // [S, 1024]
    float* out = (float*)d_out;                   // [1, 1024]

    const int S = in_sizes[1] / H;

    cos_attn_fused<<<NBLK, TPB>>>(query, keys, out, S);
}